// round 9
// baseline (speedup 1.0000x reference)
#include <cuda_runtime.h>
#include <cuda_bf16.h>
#include <cstdint>
#include <math.h>

// ---------------------------------------------------------------- constants
#define BSZ 2
#define NSEQ 4096
#define DMODEL 1024
#define NHEADS 8
#define DH 128
#define RRANK 4
#define KMAX 21
#define M_TOTAL (BSZ * NSEQ)   // 8192

// ---------------------------------------------------------------- scratch
__device__ __nv_bfloat16 g_xhi[M_TOTAL * DMODEL];
__device__ __nv_bfloat16 g_xlo[M_TOTAL * DMODEL];
__device__ __nv_bfloat16 g_phi[M_TOTAL * DMODEL];   // xproj hi
__device__ __nv_bfloat16 g_plo[M_TOTAL * DMODEL];   // xproj lo
__device__ __nv_bfloat16 g_wihi[DMODEL * DMODEL];
__device__ __nv_bfloat16 g_wilo[DMODEL * DMODEL];
__device__ __nv_bfloat16 g_wohi[DMODEL * DMODEL];
__device__ __nv_bfloat16 g_wolo[DMODEL * DMODEL];
__device__ __nv_bfloat16 g_chi[M_TOTAL * DMODEL];
__device__ __nv_bfloat16 g_clo[M_TOTAL * DMODEL];

// ---------------------------------------------------------------- helpers (base-ISA only)
__device__ __forceinline__ uint32_t smem_u32(const void* p) {
    uint32_t a;
    asm("{ .reg .u64 t; cvta.to.shared.u64 t, %1; cvt.u32.u64 %0, t; }" : "=r"(a) : "l"(p));
    return a;
}
__device__ __forceinline__ void cp_async16(uint32_t dst, const void* src) {
    asm volatile("cp.async.cg.shared.global [%0], [%1], 16;" :: "r"(dst), "l"(src));
}
__device__ __forceinline__ void ldm4(uint32_t* r, uint32_t addr) {
    asm volatile("ldmatrix.sync.aligned.m8n8.x4.shared.b16 {%0,%1,%2,%3}, [%4];"
                 : "=r"(r[0]), "=r"(r[1]), "=r"(r[2]), "=r"(r[3]) : "r"(addr));
}
__device__ __forceinline__ void mma_bf16(float* d, const uint32_t* a, uint32_t b0, uint32_t b1) {
    asm volatile(
        "mma.sync.aligned.m16n8k16.row.col.f32.bf16.bf16.f32 "
        "{%0,%1,%2,%3}, {%4,%5,%6,%7}, {%8,%9}, {%0,%1,%2,%3};"
        : "+f"(d[0]), "+f"(d[1]), "+f"(d[2]), "+f"(d[3])
        : "r"(a[0]), "r"(a[1]), "r"(a[2]), "r"(a[3]), "r"(b0), "r"(b1));
}

// ---------------------------------------------------------------- split conversion: v -> (bf16 hi, bf16 lo)
__global__ __launch_bounds__(256)
void split_bf16(const float* __restrict__ s,
                __nv_bfloat16* __restrict__ hi,
                __nv_bfloat16* __restrict__ lo, int n4)
{
    int i = blockIdx.x * blockDim.x + threadIdx.x;
    if (i >= n4) return;
    float4 v = ((const float4*)s)[i];
    __nv_bfloat16 h0 = __float2bfloat16(v.x), h1 = __float2bfloat16(v.y);
    __nv_bfloat16 h2 = __float2bfloat16(v.z), h3 = __float2bfloat16(v.w);
    __nv_bfloat16 l0 = __float2bfloat16(v.x - __bfloat162float(h0));
    __nv_bfloat16 l1 = __float2bfloat16(v.y - __bfloat162float(h1));
    __nv_bfloat16 l2 = __float2bfloat16(v.z - __bfloat162float(h2));
    __nv_bfloat16 l3 = __float2bfloat16(v.w - __bfloat162float(h3));
    ((__nv_bfloat162*)hi)[2 * i]     = __nv_bfloat162(h0, h1);
    ((__nv_bfloat162*)hi)[2 * i + 1] = __nv_bfloat162(h2, h3);
    ((__nv_bfloat162*)lo)[2 * i]     = __nv_bfloat162(l0, l1);
    ((__nv_bfloat162*)lo)[2 * i + 1] = __nv_bfloat162(l2, l3);
}

// ---------------------------------------------------------------- mma.sync GEMM: C = A @ B^T + bias (bf16 hi/lo x3)
// CTA tile 128x128, 4 warps @ 64x64, BK=16, 4-stage cp.async, 2 CTAs/SM.
// Schedule: interleave each product pass with the fragment loads it needs.
#define BM 128
#define BN 128
#define NKT 64                 // 1024 / 16
#define PITCH 48               // bytes per smem row (16 bf16 + 8 pad)
#define MATB (128 * PITCH)     // 6144 B per matrix per stage
#define STAGEB (4 * MATB)      // Ahi, Alo, Bhi, Blo = 24576 B
#define SMEM_GEMM (4 * STAGEB) // 98304 B

// one product pass: 32 independent MMAs
#define MMA_PASS(AF, BF)                                              \
    _Pragma("unroll")                                                 \
    for (int mi = 0; mi < 4; mi++) {                                  \
        _Pragma("unroll")                                             \
        for (int ni = 0; ni < 8; ni++) {                              \
            const int t = ni >> 1, pp = (ni & 1) * 2;                 \
            mma_bf16(acc[mi][ni], AF[mi], BF[t][pp], BF[t][pp + 1]);  \
        }                                                             \
    }

template<int OUT_MODE>
__global__ __launch_bounds__(128, 2)
void gemm_mma(const __nv_bfloat16* __restrict__ Ahi, const __nv_bfloat16* __restrict__ Alo,
              const __nv_bfloat16* __restrict__ Bhi, const __nv_bfloat16* __restrict__ Blo,
              const float* __restrict__ bias, float* __restrict__ C,
              __nv_bfloat16* __restrict__ Ohi, __nv_bfloat16* __restrict__ Olo)
{
    extern __shared__ char smem[];
    const uint32_t sb = smem_u32(smem);
    const int tid  = threadIdx.x;
    const int lane = tid & 31;
    const int wid  = tid >> 5;          // 0..3
    const int m0 = blockIdx.y * BM;
    const int n0 = blockIdx.x * BN;
    const int wm = (wid >> 1) * 64;     // warp m-offset
    const int wn = (wid & 1) * 64;      // warp n-offset

    const __nv_bfloat16* srcs[4] = {
        Ahi + (size_t)m0 * DMODEL, Alo + (size_t)m0 * DMODEL,
        Bhi + (size_t)n0 * DMODEL, Blo + (size_t)n0 * DMODEL };

    auto load_stage = [&](int kt, int s) {
        const uint32_t base = sb + s * STAGEB;
#pragma unroll
        for (int i = 0; i < 8; i++) {
            int g    = tid + i * 128;       // 0..1023
            int mat  = g >> 8;              // 0..3
            int rem  = g & 255;
            int row  = rem >> 1;            // 0..127
            int half = rem & 1;
            const __nv_bfloat16* src = srcs[mat] + (size_t)row * DMODEL + kt * 16 + half * 8;
            cp_async16(base + mat * MATB + row * PITCH + half * 16, src);
        }
        asm volatile("cp.async.commit_group;" ::: "memory");
    };

    float acc[4][8][4];
#pragma unroll
    for (int a = 0; a < 4; a++)
#pragma unroll
        for (int b = 0; b < 8; b++)
#pragma unroll
            for (int c = 0; c < 4; c++) acc[a][b][c] = 0.f;

    load_stage(0, 0);
    load_stage(1, 1);
    load_stage(2, 2);

    const uint32_t a_row  = (lane & 15);
    const uint32_t a_koff = (lane >> 4) * 16;
    const uint32_t b_row  = (lane & 7) + ((lane >> 4) << 3);
    const uint32_t b_koff = ((lane >> 3) & 1) * 16;

    for (int kt = 0; kt < NKT; kt++) {
        asm volatile("cp.async.wait_group 2;" ::: "memory");
        __syncthreads();

        const uint32_t stb  = sb + (kt & 3) * STAGEB;
        const uint32_t sAhi = stb;
        const uint32_t sAlo = stb + MATB;
        const uint32_t sBhi = stb + 2 * MATB;
        const uint32_t sBlo = stb + 3 * MATB;

        uint32_t ahi[4][4], alo[4][4], bhi[4][4], blo[4][4];

        // --- load hi fragments, run hi*hi while the rest streams in
#pragma unroll
        for (int t = 0; t < 4; t++)
            ldm4(bhi[t], sBhi + (wn + t * 16 + b_row) * PITCH + b_koff);
#pragma unroll
        for (int mi = 0; mi < 4; mi++)
            ldm4(ahi[mi], sAhi + (wm + mi * 16 + a_row) * PITCH + a_koff);

        MMA_PASS(ahi, bhi);   // hi*hi

        // cp.async issue burst overlaps tensor work
        if (kt + 3 < NKT) load_stage(kt + 3, (kt + 3) & 3);
        else              asm volatile("cp.async.commit_group;" ::: "memory");

#pragma unroll
        for (int t = 0; t < 4; t++)
            ldm4(blo[t], sBlo + (wn + t * 16 + b_row) * PITCH + b_koff);

        MMA_PASS(ahi, blo);   // hi*lo

#pragma unroll
        for (int mi = 0; mi < 4; mi++)
            ldm4(alo[mi], sAlo + (wm + mi * 16 + a_row) * PITCH + a_koff);

        MMA_PASS(alo, bhi);   // lo*hi
    }

    // epilogue
    const float* bs = bias + n0 + wn;
#pragma unroll
    for (int mi = 0; mi < 4; mi++) {
        int r0 = mi * 16 + (lane >> 2);
#pragma unroll
        for (int ni = 0; ni < 8; ni++) {
            int c = ni * 8 + (lane & 3) * 2;
            float b0 = bs[c], b1 = bs[c + 1];
            float v00 = acc[mi][ni][0] + b0, v01 = acc[mi][ni][1] + b1;
            float v10 = acc[mi][ni][2] + b0, v11 = acc[mi][ni][3] + b1;
            size_t off0 = (size_t)(m0 + wm + r0)     * DMODEL + n0 + wn + c;
            size_t off1 = (size_t)(m0 + wm + r0 + 8) * DMODEL + n0 + wn + c;
            if (OUT_MODE == 0) {
                *(float2*)&C[off0] = make_float2(v00, v01);
                *(float2*)&C[off1] = make_float2(v10, v11);
            } else {
                __nv_bfloat16 h00 = __float2bfloat16(v00), h01 = __float2bfloat16(v01);
                __nv_bfloat16 h10 = __float2bfloat16(v10), h11 = __float2bfloat16(v11);
                *(__nv_bfloat162*)&Ohi[off0] = __nv_bfloat162(h00, h01);
                *(__nv_bfloat162*)&Ohi[off1] = __nv_bfloat162(h10, h11);
                *(__nv_bfloat162*)&Olo[off0] = __nv_bfloat162(
                    __float2bfloat16(v00 - __bfloat162float(h00)),
                    __float2bfloat16(v01 - __bfloat162float(h01)));
                *(__nv_bfloat162*)&Olo[off1] = __nv_bfloat162(
                    __float2bfloat16(v10 - __bfloat162float(h10)),
                    __float2bfloat16(v11 - __bfloat162float(h11)));
            }
        }
    }
}

// ---------------------------------------------------------------- middle stage (fused over all heads)
#define TILE_N 32
#define MAXROWS (TILE_N + KMAX - 1)   // 52

template<int K>
__device__ __forceinline__ void dka_impl(int h, int b, int n0, int d,
    const float* __restrict__ Wc, const float* __restrict__ Aar,
    const float* __restrict__ Var, const float* __restrict__ basep,
    const float* __restrict__ alphas,
    float (*sh)[DH + 1], float* A_sh, float (*c_sh)[RRANK])
{
    constexpr int PAD  = K / 2;
    constexpr int ROWS = TILE_N + K - 1;

    const __nv_bfloat16* xh = g_phi + (size_t)b * NSEQ * DMODEL + h * DH;
    const __nv_bfloat16* xl = g_plo + (size_t)b * NSEQ * DMODEL + h * DH;
#pragma unroll
    for (int i = 0; i < ROWS; i++) {
        int n = n0 + i - PAD;
        float v = 0.f;
        if (n >= 0 && n < NSEQ) {
            size_t off = (size_t)n * DMODEL + d;
            v = __bfloat162float(xh[off]) + __bfloat162float(xl[off]);
        }
        sh[i][d] = v;
    }
    if (d < RRANK * K) {
        int r = d / K, j = d % K;
        A_sh[r * K + j] = Aar[(size_t)h * RRANK * KMAX + r * KMAX + j];
    }
    __syncthreads();

    {   // c[nl][r] = <window_center, Wc[:,r]>
        int nl = d >> 2, r = d & 3;
        const float* wc = Wc + (size_t)h * DH * RRANK + r;
        float s = 0.f;
#pragma unroll 8
        for (int dd = 0; dd < DH; dd++)
            s = fmaf(sh[nl + PAD][dd], wc[dd * RRANK], s);
        c_sh[nl][r] = s;
    }
    __syncthreads();

    const float alpha = 1.f / (1.f + expf(-alphas[h]));
    const float beta  = 1.f - alpha;

    float baser[K];
#pragma unroll
    for (int j = 0; j < K; j++)
        baser[j] = basep[((size_t)h * KMAX + j) * DH + d];
    float Vr[RRANK];
#pragma unroll
    for (int r = 0; r < RRANK; r++)
        Vr[r] = Var[((size_t)h * RRANK + r) * DH + d];

    __nv_bfloat16* ohi = g_chi + (size_t)b * NSEQ * DMODEL + h * DH + d;
    __nv_bfloat16* olo = g_clo + (size_t)b * NSEQ * DMODEL + h * DH + d;

#pragma unroll 4
    for (int nl = 0; nl < TILE_N; nl++) {
        float tb = 0.f, s0 = 0.f, s1 = 0.f, s2 = 0.f, s3 = 0.f;
#pragma unroll
        for (int j = 0; j < K; j++) {
            float xv = sh[nl + j][d];
            tb = fmaf(baser[j],        xv, tb);
            s0 = fmaf(A_sh[0 * K + j], xv, s0);
            s1 = fmaf(A_sh[1 * K + j], xv, s1);
            s2 = fmaf(A_sh[2 * K + j], xv, s2);
            s3 = fmaf(A_sh[3 * K + j], xv, s3);
        }
        float dynsum = c_sh[nl][0] * Vr[0] * s0 + c_sh[nl][1] * Vr[1] * s1
                     + c_sh[nl][2] * Vr[2] * s2 + c_sh[nl][3] * Vr[3] * s3;
        float val = alpha * dynsum + beta * tb;
        __nv_bfloat16 hv = __float2bfloat16(val);
        size_t off = (size_t)(n0 + nl) * DMODEL;
        ohi[off] = hv;
        olo[off] = __float2bfloat16(val - __bfloat162float(hv));
    }
}

__global__ __launch_bounds__(128)
void dka_mid_fused(const float* __restrict__ Wc, const float* __restrict__ Aar,
                   const float* __restrict__ Var, const float* __restrict__ basep,
                   const float* __restrict__ alphas)
{
    __shared__ float sh[MAXROWS][DH + 1];
    __shared__ float A_sh[RRANK * KMAX];
    __shared__ float c_sh[TILE_N][RRANK];

    const int d  = threadIdx.x;
    const int h  = blockIdx.y;
    const int b  = blockIdx.z;
    const int n0 = blockIdx.x * TILE_N;

    switch (h >> 1) {
        case 0: dka_impl<3 >(h, b, n0, d, Wc, Aar, Var, basep, alphas, sh, A_sh, c_sh); break;
        case 1: dka_impl<7 >(h, b, n0, d, Wc, Aar, Var, basep, alphas, sh, A_sh, c_sh); break;
        case 2: dka_impl<11>(h, b, n0, d, Wc, Aar, Var, basep, alphas, sh, A_sh, c_sh); break;
        default: dka_impl<21>(h, b, n0, d, Wc, Aar, Var, basep, alphas, sh, A_sh, c_sh); break;
    }
}

// ---------------------------------------------------------------- launch
extern "C" void kernel_launch(void* const* d_in, const int* in_sizes, int n_in,
                              void* d_out, int out_size)
{
    const float* x      = (const float*)d_in[0];
    const float* W_in   = (const float*)d_in[1];
    const float* b_in   = (const float*)d_in[2];
    const float* W_out  = (const float*)d_in[3];
    const float* b_out  = (const float*)d_in[4];
    const float* Wc     = (const float*)d_in[5];
    const float* A      = (const float*)d_in[6];
    const float* V      = (const float*)d_in[7];
    const float* basep  = (const float*)d_in[8];
    const float* alphas = (const float*)d_in[9];
    float* out = (float*)d_out;

    __nv_bfloat16 *xhi, *xlo, *phi, *plo, *wihi, *wilo, *wohi, *wolo, *chi, *clo;
    cudaGetSymbolAddress((void**)&xhi,  g_xhi);  cudaGetSymbolAddress((void**)&xlo,  g_xlo);
    cudaGetSymbolAddress((void**)&phi,  g_phi);  cudaGetSymbolAddress((void**)&plo,  g_plo);
    cudaGetSymbolAddress((void**)&wihi, g_wihi); cudaGetSymbolAddress((void**)&wilo, g_wilo);
    cudaGetSymbolAddress((void**)&wohi, g_wohi); cudaGetSymbolAddress((void**)&wolo, g_wolo);
    cudaGetSymbolAddress((void**)&chi,  g_chi);  cudaGetSymbolAddress((void**)&clo,  g_clo);

    cudaFuncSetAttribute(gemm_mma<0>, cudaFuncAttributeMaxDynamicSharedMemorySize, SMEM_GEMM);
    cudaFuncSetAttribute(gemm_mma<1>, cudaFuncAttributeMaxDynamicSharedMemorySize, SMEM_GEMM);

    // 1. split conversions
    int n4x = M_TOTAL * DMODEL / 4;
    split_bf16<<<n4x / 256, 256>>>(x, xhi, xlo, n4x);
    int n4w = DMODEL * DMODEL / 4;
    split_bf16<<<n4w / 256, 256>>>(W_in,  wihi, wilo, n4w);
    split_bf16<<<n4w / 256, 256>>>(W_out, wohi, wolo, n4w);

    dim3 ggrid(DMODEL / BN, M_TOTAL / BM);   // (8, 64)

    // 2. GEMM1: xproj(hi/lo) = x @ W_in^T + b_in
    gemm_mma<1><<<ggrid, 128, SMEM_GEMM>>>(xhi, xlo, wihi, wilo, b_in, nullptr, phi, plo);

    // 3. middle stage (fused heads), writes concat as bf16 hi/lo
    dka_mid_fused<<<dim3(NSEQ / TILE_N, NHEADS, BSZ), 128>>>(Wc, A, V, basep, alphas);

    // 4. GEMM2: out = concat @ W_out^T + b_out
    gemm_mma<0><<<ggrid, 128, SMEM_GEMM>>>(chi, clo, wohi, wolo, b_out, out, nullptr, nullptr);
}

// round 10
// speedup vs baseline: 1.4396x; 1.4396x over previous
#include <cuda_runtime.h>
#include <cuda_fp16.h>
#include <cstdint>
#include <math.h>

// ---------------------------------------------------------------- constants
#define BSZ 2
#define NSEQ 4096
#define DMODEL 1024
#define NHEADS 8
#define DH 128
#define RRANK 4
#define KMAX 21
#define M_TOTAL (BSZ * NSEQ)   // 8192

// ---------------------------------------------------------------- scratch
__device__ __half g_xhi[M_TOTAL * DMODEL];
__device__ __half g_xlo[M_TOTAL * DMODEL];
__device__ __half g_phi[M_TOTAL * DMODEL];   // xproj hi
__device__ __half g_plo[M_TOTAL * DMODEL];   // xproj lo
__device__ __half g_wi16[DMODEL * DMODEL];   // W_in fp16
__device__ __half g_wo16[DMODEL * DMODEL];   // W_out fp16
__device__ __half g_chi[M_TOTAL * DMODEL];
__device__ __half g_clo[M_TOTAL * DMODEL];

// ---------------------------------------------------------------- helpers (base-ISA only)
__device__ __forceinline__ uint32_t smem_u32(const void* p) {
    uint32_t a;
    asm("{ .reg .u64 t; cvta.to.shared.u64 t, %1; cvt.u32.u64 %0, t; }" : "=r"(a) : "l"(p));
    return a;
}
__device__ __forceinline__ void cp_async16(uint32_t dst, const void* src) {
    asm volatile("cp.async.cg.shared.global [%0], [%1], 16;" :: "r"(dst), "l"(src));
}
__device__ __forceinline__ void ldm4(uint32_t* r, uint32_t addr) {
    asm volatile("ldmatrix.sync.aligned.m8n8.x4.shared.b16 {%0,%1,%2,%3}, [%4];"
                 : "=r"(r[0]), "=r"(r[1]), "=r"(r[2]), "=r"(r[3]) : "r"(addr));
}
__device__ __forceinline__ void mma_f16(float* d, const uint32_t* a, uint32_t b0, uint32_t b1) {
    asm volatile(
        "mma.sync.aligned.m16n8k16.row.col.f32.f16.f16.f32 "
        "{%0,%1,%2,%3}, {%4,%5,%6,%7}, {%8,%9}, {%0,%1,%2,%3};"
        : "+f"(d[0]), "+f"(d[1]), "+f"(d[2]), "+f"(d[3])
        : "r"(a[0]), "r"(a[1]), "r"(a[2]), "r"(a[3]), "r"(b0), "r"(b1));
}

// ---------------------------------------------------------------- conversions
__global__ __launch_bounds__(256)
void split_f16(const float* __restrict__ s,
               __half* __restrict__ hi, __half* __restrict__ lo, int n4)
{
    int i = blockIdx.x * blockDim.x + threadIdx.x;
    if (i >= n4) return;
    float4 v = ((const float4*)s)[i];
    __half h0 = __float2half(v.x), h1 = __float2half(v.y);
    __half h2 = __float2half(v.z), h3 = __float2half(v.w);
    __half l0 = __float2half(v.x - __half2float(h0));
    __half l1 = __float2half(v.y - __half2float(h1));
    __half l2 = __float2half(v.z - __half2float(h2));
    __half l3 = __float2half(v.w - __half2float(h3));
    ((half2*)hi)[2 * i]     = half2(h0, h1);
    ((half2*)hi)[2 * i + 1] = half2(h2, h3);
    ((half2*)lo)[2 * i]     = half2(l0, l1);
    ((half2*)lo)[2 * i + 1] = half2(l2, l3);
}

__global__ __launch_bounds__(256)
void round_f16(const float* __restrict__ s, __half* __restrict__ o, int n4)
{
    int i = blockIdx.x * blockDim.x + threadIdx.x;
    if (i >= n4) return;
    float4 v = ((const float4*)s)[i];
    ((half2*)o)[2 * i]     = half2(__float2half(v.x), __float2half(v.y));
    ((half2*)o)[2 * i + 1] = half2(__float2half(v.z), __float2half(v.w));
}

// ---------------------------------------------------------------- mma.sync GEMM: C = A @ B^T + bias (fp16 hi/lo x2)
// A: M x 1024 fp16 hi/lo, B: N x 1024 fp16. CTA 128x128, 4 warps @ 64x64,
// BK=16, 4-stage cp.async, 2 CTAs/SM. R8-style batched schedule.
#define BM 128
#define BN 128
#define NKT 64                 // 1024 / 16
#define PITCH 48               // bytes per smem row (16 f16 + 8 pad)
#define MATB (128 * PITCH)     // 6144 B per matrix per stage
#define STAGEB (3 * MATB)      // Ahi, Alo, B = 18432 B
#define SMEM_GEMM (4 * STAGEB) // 73728 B

// one product pass: 32 independent MMAs
#define MMA_PASS(AF, BF)                                              \
    _Pragma("unroll")                                                 \
    for (int mi = 0; mi < 4; mi++) {                                  \
        _Pragma("unroll")                                             \
        for (int ni = 0; ni < 8; ni++) {                              \
            const int t = ni >> 1, pp = (ni & 1) * 2;                 \
            mma_f16(acc[mi][ni], AF[mi], BF[t][pp], BF[t][pp + 1]);   \
        }                                                             \
    }

template<int OUT_MODE>
__global__ __launch_bounds__(128, 2)
void gemm_mma(const __half* __restrict__ Ahi, const __half* __restrict__ Alo,
              const __half* __restrict__ Bf,
              const float* __restrict__ bias, float* __restrict__ C,
              __half* __restrict__ Ohi, __half* __restrict__ Olo)
{
    extern __shared__ char smem[];
    const uint32_t sb = smem_u32(smem);
    const int tid  = threadIdx.x;
    const int lane = tid & 31;
    const int wid  = tid >> 5;          // 0..3
    const int m0 = blockIdx.y * BM;
    const int n0 = blockIdx.x * BN;
    const int wm = (wid >> 1) * 64;     // warp m-offset
    const int wn = (wid & 1) * 64;      // warp n-offset

    const __half* srcs[3] = {
        Ahi + (size_t)m0 * DMODEL, Alo + (size_t)m0 * DMODEL,
        Bf  + (size_t)n0 * DMODEL };

    auto load_stage = [&](int kt, int s) {
        const uint32_t base = sb + s * STAGEB;
#pragma unroll
        for (int i = 0; i < 6; i++) {
            int g    = tid + i * 128;       // 0..767
            int mat  = g >> 8;              // 0..2
            int rem  = g & 255;
            int row  = rem >> 1;            // 0..127
            int half = rem & 1;
            const __half* src = srcs[mat] + (size_t)row * DMODEL + kt * 16 + half * 8;
            cp_async16(base + mat * MATB + row * PITCH + half * 16, src);
        }
        asm volatile("cp.async.commit_group;" ::: "memory");
    };

    float acc[4][8][4];
#pragma unroll
    for (int a = 0; a < 4; a++)
#pragma unroll
        for (int b = 0; b < 8; b++)
#pragma unroll
            for (int c = 0; c < 4; c++) acc[a][b][c] = 0.f;

    load_stage(0, 0);
    load_stage(1, 1);
    load_stage(2, 2);

    const uint32_t a_row  = (lane & 15);
    const uint32_t a_koff = (lane >> 4) * 16;
    const uint32_t b_row  = (lane & 7) + ((lane >> 4) << 3);
    const uint32_t b_koff = ((lane >> 3) & 1) * 16;

    for (int kt = 0; kt < NKT; kt++) {
        asm volatile("cp.async.wait_group 2;" ::: "memory");
        __syncthreads();

        if (kt + 3 < NKT) load_stage(kt + 3, (kt + 3) & 3);
        else              asm volatile("cp.async.commit_group;" ::: "memory");

        const uint32_t stb  = sb + (kt & 3) * STAGEB;
        const uint32_t sAhi = stb;
        const uint32_t sAlo = stb + MATB;
        const uint32_t sB   = stb + 2 * MATB;

        uint32_t ahi[4][4], alo[4][4], bf[4][4];
#pragma unroll
        for (int mi = 0; mi < 4; mi++) {
            uint32_t off = (wm + mi * 16 + a_row) * PITCH + a_koff;
            ldm4(ahi[mi], sAhi + off);
            ldm4(alo[mi], sAlo + off);
        }
#pragma unroll
        for (int t = 0; t < 4; t++) {
            uint32_t off = (wn + t * 16 + b_row) * PITCH + b_koff;
            ldm4(bf[t], sB + off);
        }

        MMA_PASS(ahi, bf);   // hi * B
        MMA_PASS(alo, bf);   // lo * B
    }

    // epilogue
    const float* bs = bias + n0 + wn;
#pragma unroll
    for (int mi = 0; mi < 4; mi++) {
        int r0 = mi * 16 + (lane >> 2);
#pragma unroll
        for (int ni = 0; ni < 8; ni++) {
            int c = ni * 8 + (lane & 3) * 2;
            float b0 = bs[c], b1 = bs[c + 1];
            float v00 = acc[mi][ni][0] + b0, v01 = acc[mi][ni][1] + b1;
            float v10 = acc[mi][ni][2] + b0, v11 = acc[mi][ni][3] + b1;
            size_t off0 = (size_t)(m0 + wm + r0)     * DMODEL + n0 + wn + c;
            size_t off1 = (size_t)(m0 + wm + r0 + 8) * DMODEL + n0 + wn + c;
            if (OUT_MODE == 0) {
                *(float2*)&C[off0] = make_float2(v00, v01);
                *(float2*)&C[off1] = make_float2(v10, v11);
            } else {
                __half h00 = __float2half(v00), h01 = __float2half(v01);
                __half h10 = __float2half(v10), h11 = __float2half(v11);
                *(half2*)&Ohi[off0] = half2(h00, h01);
                *(half2*)&Ohi[off1] = half2(h10, h11);
                *(half2*)&Olo[off0] = half2(__float2half(v00 - __half2float(h00)),
                                            __float2half(v01 - __half2float(h01)));
                *(half2*)&Olo[off1] = half2(__float2half(v10 - __half2float(h10)),
                                            __float2half(v11 - __half2float(h11)));
            }
        }
    }
}

// ---------------------------------------------------------------- middle stage (fused over all heads)
#define TILE_N 32
#define MAXROWS (TILE_N + KMAX - 1)   // 52

template<int K>
__device__ __forceinline__ void dka_impl(int h, int b, int n0, int d,
    const float* __restrict__ Wc, const float* __restrict__ Aar,
    const float* __restrict__ Var, const float* __restrict__ basep,
    const float* __restrict__ alphas,
    float (*sh)[DH + 1], float* A_sh, float (*c_sh)[RRANK])
{
    constexpr int PAD  = K / 2;
    constexpr int ROWS = TILE_N + K - 1;

    const __half* xh = g_phi + (size_t)b * NSEQ * DMODEL + h * DH;
    const __half* xl = g_plo + (size_t)b * NSEQ * DMODEL + h * DH;
#pragma unroll
    for (int i = 0; i < ROWS; i++) {
        int n = n0 + i - PAD;
        float v = 0.f;
        if (n >= 0 && n < NSEQ) {
            size_t off = (size_t)n * DMODEL + d;
            v = __half2float(xh[off]) + __half2float(xl[off]);
        }
        sh[i][d] = v;
    }
    if (d < RRANK * K) {
        int r = d / K, j = d % K;
        A_sh[r * K + j] = Aar[(size_t)h * RRANK * KMAX + r * KMAX + j];
    }
    __syncthreads();

    {   // c[nl][r] = <window_center, Wc[:,r]>
        int nl = d >> 2, r = d & 3;
        const float* wc = Wc + (size_t)h * DH * RRANK + r;
        float s = 0.f;
#pragma unroll 8
        for (int dd = 0; dd < DH; dd++)
            s = fmaf(sh[nl + PAD][dd], wc[dd * RRANK], s);
        c_sh[nl][r] = s;
    }
    __syncthreads();

    const float alpha = 1.f / (1.f + expf(-alphas[h]));
    const float beta  = 1.f - alpha;

    float baser[K];
#pragma unroll
    for (int j = 0; j < K; j++)
        baser[j] = basep[((size_t)h * KMAX + j) * DH + d];
    float Vr[RRANK];
#pragma unroll
    for (int r = 0; r < RRANK; r++)
        Vr[r] = Var[((size_t)h * RRANK + r) * DH + d];

    __half* ohi = g_chi + (size_t)b * NSEQ * DMODEL + h * DH + d;
    __half* olo = g_clo + (size_t)b * NSEQ * DMODEL + h * DH + d;

#pragma unroll 4
    for (int nl = 0; nl < TILE_N; nl++) {
        float tb = 0.f, s0 = 0.f, s1 = 0.f, s2 = 0.f, s3 = 0.f;
#pragma unroll
        for (int j = 0; j < K; j++) {
            float xv = sh[nl + j][d];
            tb = fmaf(baser[j],        xv, tb);
            s0 = fmaf(A_sh[0 * K + j], xv, s0);
            s1 = fmaf(A_sh[1 * K + j], xv, s1);
            s2 = fmaf(A_sh[2 * K + j], xv, s2);
            s3 = fmaf(A_sh[3 * K + j], xv, s3);
        }
        float dynsum = c_sh[nl][0] * Vr[0] * s0 + c_sh[nl][1] * Vr[1] * s1
                     + c_sh[nl][2] * Vr[2] * s2 + c_sh[nl][3] * Vr[3] * s3;
        float val = alpha * dynsum + beta * tb;
        __half hv = __float2half(val);
        size_t off = (size_t)(n0 + nl) * DMODEL;
        ohi[off] = hv;
        olo[off] = __float2half(val - __half2float(hv));
    }
}

__global__ __launch_bounds__(128)
void dka_mid_fused(const float* __restrict__ Wc, const float* __restrict__ Aar,
                   const float* __restrict__ Var, const float* __restrict__ basep,
                   const float* __restrict__ alphas)
{
    __shared__ float sh[MAXROWS][DH + 1];
    __shared__ float A_sh[RRANK * KMAX];
    __shared__ float c_sh[TILE_N][RRANK];

    const int d  = threadIdx.x;
    const int h  = blockIdx.y;
    const int b  = blockIdx.z;
    const int n0 = blockIdx.x * TILE_N;

    switch (h >> 1) {
        case 0: dka_impl<3 >(h, b, n0, d, Wc, Aar, Var, basep, alphas, sh, A_sh, c_sh); break;
        case 1: dka_impl<7 >(h, b, n0, d, Wc, Aar, Var, basep, alphas, sh, A_sh, c_sh); break;
        case 2: dka_impl<11>(h, b, n0, d, Wc, Aar, Var, basep, alphas, sh, A_sh, c_sh); break;
        default: dka_impl<21>(h, b, n0, d, Wc, Aar, Var, basep, alphas, sh, A_sh, c_sh); break;
    }
}

// ---------------------------------------------------------------- launch
extern "C" void kernel_launch(void* const* d_in, const int* in_sizes, int n_in,
                              void* d_out, int out_size)
{
    const float* x      = (const float*)d_in[0];
    const float* W_in   = (const float*)d_in[1];
    const float* b_in   = (const float*)d_in[2];
    const float* W_out  = (const float*)d_in[3];
    const float* b_out  = (const float*)d_in[4];
    const float* Wc     = (const float*)d_in[5];
    const float* A      = (const float*)d_in[6];
    const float* V      = (const float*)d_in[7];
    const float* basep  = (const float*)d_in[8];
    const float* alphas = (const float*)d_in[9];
    float* out = (float*)d_out;

    __half *xhi, *xlo, *phi, *plo, *wi16, *wo16, *chi, *clo;
    cudaGetSymbolAddress((void**)&xhi,  g_xhi);  cudaGetSymbolAddress((void**)&xlo,  g_xlo);
    cudaGetSymbolAddress((void**)&phi,  g_phi);  cudaGetSymbolAddress((void**)&plo,  g_plo);
    cudaGetSymbolAddress((void**)&wi16, g_wi16); cudaGetSymbolAddress((void**)&wo16, g_wo16);
    cudaGetSymbolAddress((void**)&chi,  g_chi);  cudaGetSymbolAddress((void**)&clo,  g_clo);

    cudaFuncSetAttribute(gemm_mma<0>, cudaFuncAttributeMaxDynamicSharedMemorySize, SMEM_GEMM);
    cudaFuncSetAttribute(gemm_mma<1>, cudaFuncAttributeMaxDynamicSharedMemorySize, SMEM_GEMM);

    // 1. conversions
    int n4x = M_TOTAL * DMODEL / 4;
    split_f16<<<n4x / 256, 256>>>(x, xhi, xlo, n4x);
    int n4w = DMODEL * DMODEL / 4;
    round_f16<<<n4w / 256, 256>>>(W_in,  wi16, n4w);
    round_f16<<<n4w / 256, 256>>>(W_out, wo16, n4w);

    dim3 ggrid(DMODEL / BN, M_TOTAL / BM);   // (8, 64)

    // 2. GEMM1: xproj(hi/lo) = x @ W_in^T + b_in
    gemm_mma<1><<<ggrid, 128, SMEM_GEMM>>>(xhi, xlo, wi16, b_in, nullptr, phi, plo);

    // 3. middle stage (fused heads), writes concat as fp16 hi/lo
    dka_mid_fused<<<dim3(NSEQ / TILE_N, NHEADS, BSZ), 128>>>(Wc, A, V, basep, alphas);

    // 4. GEMM2: out = concat @ W_out^T + b_out
    gemm_mma<0><<<ggrid, 128, SMEM_GEMM>>>(chi, clo, wo16, b_out, out, nullptr, nullptr);
}

// round 12
// speedup vs baseline: 1.5166x; 1.0535x over previous
#include <cuda_runtime.h>
#include <cuda_fp16.h>
#include <cstdint>
#include <math.h>

// ---------------------------------------------------------------- constants
#define BSZ 2
#define NSEQ 4096
#define DMODEL 1024
#define NHEADS 8
#define DH 128
#define RRANK 4
#define KMAX 21
#define M_TOTAL (BSZ * NSEQ)   // 8192

// ---------------------------------------------------------------- scratch
__device__ __half g_xhi[M_TOTAL * DMODEL];
__device__ __half g_xlo[M_TOTAL * DMODEL];
__device__ __half g_phi[M_TOTAL * DMODEL];   // xproj hi
__device__ __half g_plo[M_TOTAL * DMODEL];   // xproj lo
__device__ __half g_wi16[DMODEL * DMODEL];   // W_in fp16
__device__ __half g_wo16[DMODEL * DMODEL];   // W_out fp16
__device__ __half g_chi[M_TOTAL * DMODEL];
__device__ __half g_clo[M_TOTAL * DMODEL];

// ---------------------------------------------------------------- helpers (base-ISA only)
__device__ __forceinline__ uint32_t smem_u32(const void* p) {
    uint32_t a;
    asm("{ .reg .u64 t; cvta.to.shared.u64 t, %1; cvt.u32.u64 %0, t; }" : "=r"(a) : "l"(p));
    return a;
}
__device__ __forceinline__ void cp_async16(uint32_t dst, const void* src) {
    asm volatile("cp.async.cg.shared.global [%0], [%1], 16;" :: "r"(dst), "l"(src));
}
__device__ __forceinline__ void ldm4(uint32_t* r, uint32_t addr) {
    asm volatile("ldmatrix.sync.aligned.m8n8.x4.shared.b16 {%0,%1,%2,%3}, [%4];"
                 : "=r"(r[0]), "=r"(r[1]), "=r"(r[2]), "=r"(r[3]) : "r"(addr));
}
__device__ __forceinline__ void mma_f16(float* d, const uint32_t* a, uint32_t b0, uint32_t b1) {
    asm volatile(
        "mma.sync.aligned.m16n8k16.row.col.f32.f16.f16.f32 "
        "{%0,%1,%2,%3}, {%4,%5,%6,%7}, {%8,%9}, {%0,%1,%2,%3};"
        : "+f"(d[0]), "+f"(d[1]), "+f"(d[2]), "+f"(d[3])
        : "r"(a[0]), "r"(a[1]), "r"(a[2]), "r"(a[3]), "r"(b0), "r"(b1));
}

// ---------------------------------------------------------------- conversions
__global__ __launch_bounds__(256)
void split_f16(const float* __restrict__ s,
               __half* __restrict__ hi, __half* __restrict__ lo, int n4)
{
    int i = blockIdx.x * blockDim.x + threadIdx.x;
    if (i >= n4) return;
    float4 v = ((const float4*)s)[i];
    __half h0 = __float2half(v.x), h1 = __float2half(v.y);
    __half h2 = __float2half(v.z), h3 = __float2half(v.w);
    __half l0 = __float2half(v.x - __half2float(h0));
    __half l1 = __float2half(v.y - __half2float(h1));
    __half l2 = __float2half(v.z - __half2float(h2));
    __half l3 = __float2half(v.w - __half2float(h3));
    ((half2*)hi)[2 * i]     = half2(h0, h1);
    ((half2*)hi)[2 * i + 1] = half2(h2, h3);
    ((half2*)lo)[2 * i]     = half2(l0, l1);
    ((half2*)lo)[2 * i + 1] = half2(l2, l3);
}

__global__ __launch_bounds__(256)
void round_f16(const float* __restrict__ s, __half* __restrict__ o, int n4)
{
    int i = blockIdx.x * blockDim.x + threadIdx.x;
    if (i >= n4) return;
    float4 v = ((const float4*)s)[i];
    ((half2*)o)[2 * i]     = half2(__float2half(v.x), __float2half(v.y));
    ((half2*)o)[2 * i + 1] = half2(__float2half(v.z), __float2half(v.w));
}

// ---------------------------------------------------------------- mma.sync GEMM: C = A @ B^T + bias (fp16 hi/lo x2)
// CTA 128x128, 4 warps @ 64x64, BK=16, 4-stage cp.async, 2 CTAs/SM,
// cross-iteration fragment double-buffering (race-free: barrier between
// wait_group and any smem read).
#define BM 128
#define BN 128
#define NKT 64                 // 1024 / 16
#define PITCH 48               // bytes per smem row (16 f16 + 8 pad)
#define MATB (128 * PITCH)     // 6144 B per matrix per stage
#define STAGEB (3 * MATB)      // Ahi, Alo, B = 18432 B
#define SMEM_GEMM (4 * STAGEB) // 73728 B

// one product pass: 32 independent MMAs
#define MMA_PASS(AF, BF)                                              \
    _Pragma("unroll")                                                 \
    for (int mi = 0; mi < 4; mi++) {                                  \
        _Pragma("unroll")                                             \
        for (int ni = 0; ni < 8; ni++) {                              \
            const int t = ni >> 1, pp = (ni & 1) * 2;                 \
            mma_f16(acc[mi][ni], AF[mi], BF[t][pp], BF[t][pp + 1]);   \
        }                                                             \
    }

template<int OUT_MODE>
__global__ __launch_bounds__(128, 2)
void gemm_mma(const __half* __restrict__ Ahi, const __half* __restrict__ Alo,
              const __half* __restrict__ Bf,
              const float* __restrict__ bias, float* __restrict__ C,
              __half* __restrict__ Ohi, __half* __restrict__ Olo)
{
    extern __shared__ char smem[];
    const uint32_t sb = smem_u32(smem);
    const int tid  = threadIdx.x;
    const int lane = tid & 31;
    const int wid  = tid >> 5;          // 0..3
    const int m0 = blockIdx.y * BM;
    const int n0 = blockIdx.x * BN;
    const int wm = (wid >> 1) * 64;     // warp m-offset
    const int wn = (wid & 1) * 64;      // warp n-offset

    const __half* srcs[3] = {
        Ahi + (size_t)m0 * DMODEL, Alo + (size_t)m0 * DMODEL,
        Bf  + (size_t)n0 * DMODEL };

    auto load_stage = [&](int kt, int s) {
        const uint32_t base = sb + s * STAGEB;
#pragma unroll
        for (int i = 0; i < 6; i++) {
            int g    = tid + i * 128;       // 0..767
            int mat  = g >> 8;              // 0..2
            int rem  = g & 255;
            int row  = rem >> 1;            // 0..127
            int half = rem & 1;
            const __half* src = srcs[mat] + (size_t)row * DMODEL + kt * 16 + half * 8;
            cp_async16(base + mat * MATB + row * PITCH + half * 16, src);
        }
        asm volatile("cp.async.commit_group;" ::: "memory");
    };

    const uint32_t a_row  = (lane & 15);
    const uint32_t a_koff = (lane >> 4) * 16;
    const uint32_t b_row  = (lane & 7) + ((lane >> 4) << 3);
    const uint32_t b_koff = ((lane >> 3) & 1) * 16;

    // fragment buffers (double-buffered across iterations)
    uint32_t fahi[2][4][4], falo[2][4][4], fb[2][4][4];
    auto load_frags = [&](int s, int buf) {
        const uint32_t stb = sb + s * STAGEB;
#pragma unroll
        for (int mi = 0; mi < 4; mi++) {
            uint32_t off = (wm + mi * 16 + a_row) * PITCH + a_koff;
            ldm4(fahi[buf][mi], stb + off);
            ldm4(falo[buf][mi], stb + MATB + off);
        }
#pragma unroll
        for (int t = 0; t < 4; t++) {
            uint32_t off = (wn + t * 16 + b_row) * PITCH + b_koff;
            ldm4(fb[buf][t], stb + 2 * MATB + off);
        }
    };

    float acc[4][8][4];
#pragma unroll
    for (int a = 0; a < 4; a++)
#pragma unroll
        for (int b = 0; b < 8; b++)
#pragma unroll
            for (int c = 0; c < 4; c++) acc[a][b][c] = 0.f;

    load_stage(0, 0);
    load_stage(1, 1);
    load_stage(2, 2);

    asm volatile("cp.async.wait_group 2;" ::: "memory");  // this thread: stage 0 done
    __syncthreads();                                      // all threads: stage 0 done
    load_frags(0, 0);

#pragma unroll 2
    for (int kt = 0; kt < NKT; kt++) {
        const int cur = kt & 1, nxt = cur ^ 1;

        // this thread's groups through stage kt+1 complete...
        asm volatile("cp.async.wait_group 1;" ::: "memory");
        // ...and after the barrier, ALL threads' copies for stage kt+1 complete.
        // Also serves as the WAR fence before load_stage overwrites slot kt-1.
        __syncthreads();

        if (kt + 1 < NKT) load_frags((kt + 1) & 3, nxt);   // prefetch under MMAs

        MMA_PASS(fahi[cur], fb[cur]);   // hi * B
        MMA_PASS(falo[cur], fb[cur]);   // lo * B

        if (kt + 3 < NKT) load_stage(kt + 3, (kt + 3) & 3);
        else              asm volatile("cp.async.commit_group;" ::: "memory");
    }

    // epilogue
    const float* bs = bias + n0 + wn;
#pragma unroll
    for (int mi = 0; mi < 4; mi++) {
        int r0 = mi * 16 + (lane >> 2);
#pragma unroll
        for (int ni = 0; ni < 8; ni++) {
            int c = ni * 8 + (lane & 3) * 2;
            float b0 = bs[c], b1 = bs[c + 1];
            float v00 = acc[mi][ni][0] + b0, v01 = acc[mi][ni][1] + b1;
            float v10 = acc[mi][ni][2] + b0, v11 = acc[mi][ni][3] + b1;
            size_t off0 = (size_t)(m0 + wm + r0)     * DMODEL + n0 + wn + c;
            size_t off1 = (size_t)(m0 + wm + r0 + 8) * DMODEL + n0 + wn + c;
            if (OUT_MODE == 0) {
                *(float2*)&C[off0] = make_float2(v00, v01);
                *(float2*)&C[off1] = make_float2(v10, v11);
            } else {
                __half h00 = __float2half(v00), h01 = __float2half(v01);
                __half h10 = __float2half(v10), h11 = __float2half(v11);
                *(half2*)&Ohi[off0] = half2(h00, h01);
                *(half2*)&Ohi[off1] = half2(h10, h11);
                *(half2*)&Olo[off0] = half2(__float2half(v00 - __half2float(h00)),
                                            __float2half(v01 - __half2float(h01)));
                *(half2*)&Olo[off1] = half2(__float2half(v10 - __half2float(h10)),
                                            __float2half(v11 - __half2float(h11)));
            }
        }
    }
}

// ---------------------------------------------------------------- middle stage (fused over all heads)
#define TILE_N 32
#define MAXROWS (TILE_N + KMAX - 1)   // 52

template<int K>
__device__ __forceinline__ void dka_impl(int h, int b, int n0, int d,
    const float* __restrict__ Wc, const float* __restrict__ Aar,
    const float* __restrict__ Var, const float* __restrict__ basep,
    const float* __restrict__ alphas,
    float (*sh)[DH + 1], float* A_sh, float (*c_sh)[RRANK])
{
    constexpr int PAD  = K / 2;
    constexpr int ROWS = TILE_N + K - 1;

    const __half* xh = g_phi + (size_t)b * NSEQ * DMODEL + h * DH;
    const __half* xl = g_plo + (size_t)b * NSEQ * DMODEL + h * DH;
#pragma unroll
    for (int i = 0; i < ROWS; i++) {
        int n = n0 + i - PAD;
        float v = 0.f;
        if (n >= 0 && n < NSEQ) {
            size_t off = (size_t)n * DMODEL + d;
            v = __half2float(xh[off]) + __half2float(xl[off]);
        }
        sh[i][d] = v;
    }
    if (d < RRANK * K) {
        int r = d / K, j = d % K;
        A_sh[r * K + j] = Aar[(size_t)h * RRANK * KMAX + r * KMAX + j];
    }
    __syncthreads();

    {   // c[nl][r] = <window_center, Wc[:,r]>
        int nl = d >> 2, r = d & 3;
        const float* wc = Wc + (size_t)h * DH * RRANK + r;
        float s = 0.f;
#pragma unroll 8
        for (int dd = 0; dd < DH; dd++)
            s = fmaf(sh[nl + PAD][dd], wc[dd * RRANK], s);
        c_sh[nl][r] = s;
    }
    __syncthreads();

    const float alpha = 1.f / (1.f + expf(-alphas[h]));
    const float beta  = 1.f - alpha;

    float baser[K];
#pragma unroll
    for (int j = 0; j < K; j++)
        baser[j] = basep[((size_t)h * KMAX + j) * DH + d];
    float Vr[RRANK];
#pragma unroll
    for (int r = 0; r < RRANK; r++)
        Vr[r] = Var[((size_t)h * RRANK + r) * DH + d];

    __half* ohi = g_chi + (size_t)b * NSEQ * DMODEL + h * DH + d;
    __half* olo = g_clo + (size_t)b * NSEQ * DMODEL + h * DH + d;

#pragma unroll 4
    for (int nl = 0; nl < TILE_N; nl++) {
        float tb = 0.f, s0 = 0.f, s1 = 0.f, s2 = 0.f, s3 = 0.f;
#pragma unroll
        for (int j = 0; j < K; j++) {
            float xv = sh[nl + j][d];
            tb = fmaf(baser[j],        xv, tb);
            s0 = fmaf(A_sh[0 * K + j], xv, s0);
            s1 = fmaf(A_sh[1 * K + j], xv, s1);
            s2 = fmaf(A_sh[2 * K + j], xv, s2);
            s3 = fmaf(A_sh[3 * K + j], xv, s3);
        }
        float dynsum = c_sh[nl][0] * Vr[0] * s0 + c_sh[nl][1] * Vr[1] * s1
                     + c_sh[nl][2] * Vr[2] * s2 + c_sh[nl][3] * Vr[3] * s3;
        float val = alpha * dynsum + beta * tb;
        __half hv = __float2half(val);
        size_t off = (size_t)(n0 + nl) * DMODEL;
        ohi[off] = hv;
        olo[off] = __float2half(val - __half2float(hv));
    }
}

__global__ __launch_bounds__(128)
void dka_mid_fused(const float* __restrict__ Wc, const float* __restrict__ Aar,
                   const float* __restrict__ Var, const float* __restrict__ basep,
                   const float* __restrict__ alphas)
{
    __shared__ float sh[MAXROWS][DH + 1];
    __shared__ float A_sh[RRANK * KMAX];
    __shared__ float c_sh[TILE_N][RRANK];

    const int d  = threadIdx.x;
    const int h  = blockIdx.y;
    const int b  = blockIdx.z;
    const int n0 = blockIdx.x * TILE_N;

    switch (h >> 1) {
        case 0: dka_impl<3 >(h, b, n0, d, Wc, Aar, Var, basep, alphas, sh, A_sh, c_sh); break;
        case 1: dka_impl<7 >(h, b, n0, d, Wc, Aar, Var, basep, alphas, sh, A_sh, c_sh); break;
        case 2: dka_impl<11>(h, b, n0, d, Wc, Aar, Var, basep, alphas, sh, A_sh, c_sh); break;
        default: dka_impl<21>(h, b, n0, d, Wc, Aar, Var, basep, alphas, sh, A_sh, c_sh); break;
    }
}

// ---------------------------------------------------------------- launch
extern "C" void kernel_launch(void* const* d_in, const int* in_sizes, int n_in,
                              void* d_out, int out_size)
{
    const float* x      = (const float*)d_in[0];
    const float* W_in   = (const float*)d_in[1];
    const float* b_in   = (const float*)d_in[2];
    const float* W_out  = (const float*)d_in[3];
    const float* b_out  = (const float*)d_in[4];
    const float* Wc     = (const float*)d_in[5];
    const float* A      = (const float*)d_in[6];
    const float* V      = (const float*)d_in[7];
    const float* basep  = (const float*)d_in[8];
    const float* alphas = (const float*)d_in[9];
    float* out = (float*)d_out;

    __half *xhi, *xlo, *phi, *plo, *wi16, *wo16, *chi, *clo;
    cudaGetSymbolAddress((void**)&xhi,  g_xhi);  cudaGetSymbolAddress((void**)&xlo,  g_xlo);
    cudaGetSymbolAddress((void**)&phi,  g_phi);  cudaGetSymbolAddress((void**)&plo,  g_plo);
    cudaGetSymbolAddress((void**)&wi16, g_wi16); cudaGetSymbolAddress((void**)&wo16, g_wo16);
    cudaGetSymbolAddress((void**)&chi,  g_chi);  cudaGetSymbolAddress((void**)&clo,  g_clo);

    cudaFuncSetAttribute(gemm_mma<0>, cudaFuncAttributeMaxDynamicSharedMemorySize, SMEM_GEMM);
    cudaFuncSetAttribute(gemm_mma<1>, cudaFuncAttributeMaxDynamicSharedMemorySize, SMEM_GEMM);

    // 1. conversions
    int n4x = M_TOTAL * DMODEL / 4;
    split_f16<<<n4x / 256, 256>>>(x, xhi, xlo, n4x);
    int n4w = DMODEL * DMODEL / 4;
    round_f16<<<n4w / 256, 256>>>(W_in,  wi16, n4w);
    round_f16<<<n4w / 256, 256>>>(W_out, wo16, n4w);

    dim3 ggrid(DMODEL / BN, M_TOTAL / BM);   // (8, 64)

    // 2. GEMM1: xproj(hi/lo) = x @ W_in^T + b_in
    gemm_mma<1><<<ggrid, 128, SMEM_GEMM>>>(xhi, xlo, wi16, b_in, nullptr, phi, plo);

    // 3. middle stage (fused heads), writes concat as fp16 hi/lo
    dka_mid_fused<<<dim3(NSEQ / TILE_N, NHEADS, BSZ), 128>>>(Wc, A, V, basep, alphas);

    // 4. GEMM2: out = concat @ W_out^T + b_out
    gemm_mma<0><<<ggrid, 128, SMEM_GEMM>>>(chi, clo, wo16, b_out, out, nullptr, nullptr);
}

// round 13
// speedup vs baseline: 1.9129x; 1.2613x over previous
#include <cuda_runtime.h>
#include <cuda_fp16.h>
#include <cstdint>
#include <math.h>

// ---------------------------------------------------------------- constants
#define BSZ 2
#define NSEQ 4096
#define DMODEL 1024
#define NHEADS 8
#define DH 128
#define RRANK 4
#define KMAX 21
#define M_TOTAL (BSZ * NSEQ)   // 8192

// ---------------------------------------------------------------- scratch
__device__ __half g_x16[M_TOTAL * DMODEL];   // x fp16
__device__ __half g_phi[M_TOTAL * DMODEL];   // xproj hi
__device__ __half g_plo[M_TOTAL * DMODEL];   // xproj lo
__device__ __half g_wi16[DMODEL * DMODEL];   // W_in fp16
__device__ __half g_wo16[DMODEL * DMODEL];   // W_out fp16
__device__ __half g_c16[M_TOTAL * DMODEL];   // concat fp16

// ---------------------------------------------------------------- helpers (base-ISA only)
__device__ __forceinline__ uint32_t smem_u32(const void* p) {
    uint32_t a;
    asm("{ .reg .u64 t; cvta.to.shared.u64 t, %1; cvt.u32.u64 %0, t; }" : "=r"(a) : "l"(p));
    return a;
}
__device__ __forceinline__ void cp_async16(uint32_t dst, const void* src) {
    asm volatile("cp.async.cg.shared.global [%0], [%1], 16;" :: "r"(dst), "l"(src));
}
__device__ __forceinline__ void ldm4(uint32_t* r, uint32_t addr) {
    asm volatile("ldmatrix.sync.aligned.m8n8.x4.shared.b16 {%0,%1,%2,%3}, [%4];"
                 : "=r"(r[0]), "=r"(r[1]), "=r"(r[2]), "=r"(r[3]) : "r"(addr));
}
__device__ __forceinline__ void mma_f16(float* d, const uint32_t* a, uint32_t b0, uint32_t b1) {
    asm volatile(
        "mma.sync.aligned.m16n8k16.row.col.f32.f16.f16.f32 "
        "{%0,%1,%2,%3}, {%4,%5,%6,%7}, {%8,%9}, {%0,%1,%2,%3};"
        : "+f"(d[0]), "+f"(d[1]), "+f"(d[2]), "+f"(d[3])
        : "r"(a[0]), "r"(a[1]), "r"(a[2]), "r"(a[3]), "r"(b0), "r"(b1));
}

// ---------------------------------------------------------------- conversion
__global__ __launch_bounds__(256)
void round_f16(const float* __restrict__ s, __half* __restrict__ o, int n4)
{
    int i = blockIdx.x * blockDim.x + threadIdx.x;
    if (i >= n4) return;
    float4 v = ((const float4*)s)[i];
    ((half2*)o)[2 * i]     = half2(__float2half(v.x), __float2half(v.y));
    ((half2*)o)[2 * i + 1] = half2(__float2half(v.z), __float2half(v.w));
}

// ---------------------------------------------------------------- mma.sync GEMM: C = A @ B^T + bias (single-pass fp16)
// CTA 128x128, 4 warps @ 64x64, BK=16, 4-stage cp.async, 2 CTAs/SM,
// cross-iteration fragment double-buffering.
#define BM 128
#define BN 128
#define NKT 64                 // 1024 / 16
#define PITCH 48               // bytes per smem row (16 f16 + 8 pad)
#define MATB (128 * PITCH)     // 6144 B per matrix per stage
#define STAGEB (2 * MATB)      // A, B = 12288 B
#define SMEM_GEMM (4 * STAGEB) // 49152 B

template<int OUT_MODE>
__global__ __launch_bounds__(128, 2)
void gemm_mma(const __half* __restrict__ Af, const __half* __restrict__ Bf,
              const float* __restrict__ bias, float* __restrict__ C,
              __half* __restrict__ Ohi, __half* __restrict__ Olo)
{
    extern __shared__ char smem[];
    const uint32_t sb = smem_u32(smem);
    const int tid  = threadIdx.x;
    const int lane = tid & 31;
    const int wid  = tid >> 5;          // 0..3
    const int m0 = blockIdx.y * BM;
    const int n0 = blockIdx.x * BN;
    const int wm = (wid >> 1) * 64;     // warp m-offset
    const int wn = (wid & 1) * 64;      // warp n-offset

    const __half* srcs[2] = { Af + (size_t)m0 * DMODEL, Bf + (size_t)n0 * DMODEL };

    auto load_stage = [&](int kt, int s) {
        const uint32_t base = sb + s * STAGEB;
#pragma unroll
        for (int i = 0; i < 4; i++) {
            int g    = tid + i * 128;       // 0..511
            int mat  = g >> 8;              // 0..1
            int rem  = g & 255;
            int row  = rem >> 1;            // 0..127
            int half = rem & 1;
            const __half* src = srcs[mat] + (size_t)row * DMODEL + kt * 16 + half * 8;
            cp_async16(base + mat * MATB + row * PITCH + half * 16, src);
        }
        asm volatile("cp.async.commit_group;" ::: "memory");
    };

    const uint32_t a_row  = (lane & 15);
    const uint32_t a_koff = (lane >> 4) * 16;
    const uint32_t b_row  = (lane & 7) + ((lane >> 4) << 3);
    const uint32_t b_koff = ((lane >> 3) & 1) * 16;

    // fragment buffers (double-buffered across iterations)
    uint32_t fa[2][4][4], fb[2][4][4];
    auto load_frags = [&](int s, int buf) {
        const uint32_t stb = sb + s * STAGEB;
#pragma unroll
        for (int mi = 0; mi < 4; mi++)
            ldm4(fa[buf][mi], stb + (wm + mi * 16 + a_row) * PITCH + a_koff);
#pragma unroll
        for (int t = 0; t < 4; t++)
            ldm4(fb[buf][t], stb + MATB + (wn + t * 16 + b_row) * PITCH + b_koff);
    };

    float acc[4][8][4];
#pragma unroll
    for (int a = 0; a < 4; a++)
#pragma unroll
        for (int b = 0; b < 8; b++)
#pragma unroll
            for (int c = 0; c < 4; c++) acc[a][b][c] = 0.f;

    load_stage(0, 0);
    load_stage(1, 1);
    load_stage(2, 2);

    asm volatile("cp.async.wait_group 2;" ::: "memory");  // this thread: stage 0 done
    __syncthreads();                                      // all threads: stage 0 done
    load_frags(0, 0);

#pragma unroll 2
    for (int kt = 0; kt < NKT; kt++) {
        const int cur = kt & 1, nxt = cur ^ 1;

        asm volatile("cp.async.wait_group 1;" ::: "memory");
        __syncthreads();   // all threads' stage kt+1 complete; WAR fence for slot kt-1

        if (kt + 1 < NKT) load_frags((kt + 1) & 3, nxt);   // prefetch under MMAs

#pragma unroll
        for (int mi = 0; mi < 4; mi++)
#pragma unroll
            for (int ni = 0; ni < 8; ni++) {
                const int t = ni >> 1, pp = (ni & 1) * 2;
                mma_f16(acc[mi][ni], fa[cur][mi], fb[cur][t][pp], fb[cur][t][pp + 1]);
            }

        if (kt + 3 < NKT) load_stage(kt + 3, (kt + 3) & 3);
        else              asm volatile("cp.async.commit_group;" ::: "memory");
    }

    // epilogue
    const float* bs = bias + n0 + wn;
#pragma unroll
    for (int mi = 0; mi < 4; mi++) {
        int r0 = mi * 16 + (lane >> 2);
#pragma unroll
        for (int ni = 0; ni < 8; ni++) {
            int c = ni * 8 + (lane & 3) * 2;
            float b0 = bs[c], b1 = bs[c + 1];
            float v00 = acc[mi][ni][0] + b0, v01 = acc[mi][ni][1] + b1;
            float v10 = acc[mi][ni][2] + b0, v11 = acc[mi][ni][3] + b1;
            size_t off0 = (size_t)(m0 + wm + r0)     * DMODEL + n0 + wn + c;
            size_t off1 = (size_t)(m0 + wm + r0 + 8) * DMODEL + n0 + wn + c;
            if (OUT_MODE == 0) {
                *(float2*)&C[off0] = make_float2(v00, v01);
                *(float2*)&C[off1] = make_float2(v10, v11);
            } else {
                __half h00 = __float2half(v00), h01 = __float2half(v01);
                __half h10 = __float2half(v10), h11 = __float2half(v11);
                *(half2*)&Ohi[off0] = half2(h00, h01);
                *(half2*)&Ohi[off1] = half2(h10, h11);
                *(half2*)&Olo[off0] = half2(__float2half(v00 - __half2float(h00)),
                                            __float2half(v01 - __half2float(h01)));
                *(half2*)&Olo[off1] = half2(__float2half(v10 - __half2float(h10)),
                                            __float2half(v11 - __half2float(h11)));
            }
        }
    }
}

// ---------------------------------------------------------------- middle stage (fused over all heads)
#define TILE_N 32
#define MAXROWS (TILE_N + KMAX - 1)   // 52

template<int K>
__device__ __forceinline__ void dka_impl(int h, int b, int n0, int d,
    const float* __restrict__ Wc, const float* __restrict__ Aar,
    const float* __restrict__ Var, const float* __restrict__ basep,
    const float* __restrict__ alphas,
    float (*sh)[DH + 1], float* A_sh, float (*c_sh)[RRANK])
{
    constexpr int PAD  = K / 2;
    constexpr int ROWS = TILE_N + K - 1;

    const __half* xh = g_phi + (size_t)b * NSEQ * DMODEL + h * DH;
    const __half* xl = g_plo + (size_t)b * NSEQ * DMODEL + h * DH;
#pragma unroll
    for (int i = 0; i < ROWS; i++) {
        int n = n0 + i - PAD;
        float v = 0.f;
        if (n >= 0 && n < NSEQ) {
            size_t off = (size_t)n * DMODEL + d;
            v = __half2float(xh[off]) + __half2float(xl[off]);
        }
        sh[i][d] = v;
    }
    if (d < RRANK * K) {
        int r = d / K, j = d % K;
        A_sh[r * K + j] = Aar[(size_t)h * RRANK * KMAX + r * KMAX + j];
    }
    __syncthreads();

    {   // c[nl][r] = <window_center, Wc[:,r]>
        int nl = d >> 2, r = d & 3;
        const float* wc = Wc + (size_t)h * DH * RRANK + r;
        float s = 0.f;
#pragma unroll 8
        for (int dd = 0; dd < DH; dd++)
            s = fmaf(sh[nl + PAD][dd], wc[dd * RRANK], s);
        c_sh[nl][r] = s;
    }
    __syncthreads();

    const float alpha = 1.f / (1.f + expf(-alphas[h]));
    const float beta  = 1.f - alpha;

    float baser[K];
#pragma unroll
    for (int j = 0; j < K; j++)
        baser[j] = basep[((size_t)h * KMAX + j) * DH + d];
    float Vr[RRANK];
#pragma unroll
    for (int r = 0; r < RRANK; r++)
        Vr[r] = Var[((size_t)h * RRANK + r) * DH + d];

    __half* oc = g_c16 + (size_t)b * NSEQ * DMODEL + h * DH + d;

#pragma unroll 4
    for (int nl = 0; nl < TILE_N; nl++) {
        float tb = 0.f, s0 = 0.f, s1 = 0.f, s2 = 0.f, s3 = 0.f;
#pragma unroll
        for (int j = 0; j < K; j++) {
            float xv = sh[nl + j][d];
            tb = fmaf(baser[j],        xv, tb);
            s0 = fmaf(A_sh[0 * K + j], xv, s0);
            s1 = fmaf(A_sh[1 * K + j], xv, s1);
            s2 = fmaf(A_sh[2 * K + j], xv, s2);
            s3 = fmaf(A_sh[3 * K + j], xv, s3);
        }
        float dynsum = c_sh[nl][0] * Vr[0] * s0 + c_sh[nl][1] * Vr[1] * s1
                     + c_sh[nl][2] * Vr[2] * s2 + c_sh[nl][3] * Vr[3] * s3;
        float val = alpha * dynsum + beta * tb;
        oc[(size_t)(n0 + nl) * DMODEL] = __float2half(val);
    }
}

__global__ __launch_bounds__(128)
void dka_mid_fused(const float* __restrict__ Wc, const float* __restrict__ Aar,
                   const float* __restrict__ Var, const float* __restrict__ basep,
                   const float* __restrict__ alphas)
{
    __shared__ float sh[MAXROWS][DH + 1];
    __shared__ float A_sh[RRANK * KMAX];
    __shared__ float c_sh[TILE_N][RRANK];

    const int d  = threadIdx.x;
    const int h  = blockIdx.y;
    const int b  = blockIdx.z;
    const int n0 = blockIdx.x * TILE_N;

    switch (h >> 1) {
        case 0: dka_impl<3 >(h, b, n0, d, Wc, Aar, Var, basep, alphas, sh, A_sh, c_sh); break;
        case 1: dka_impl<7 >(h, b, n0, d, Wc, Aar, Var, basep, alphas, sh, A_sh, c_sh); break;
        case 2: dka_impl<11>(h, b, n0, d, Wc, Aar, Var, basep, alphas, sh, A_sh, c_sh); break;
        default: dka_impl<21>(h, b, n0, d, Wc, Aar, Var, basep, alphas, sh, A_sh, c_sh); break;
    }
}

// ---------------------------------------------------------------- launch
extern "C" void kernel_launch(void* const* d_in, const int* in_sizes, int n_in,
                              void* d_out, int out_size)
{
    const float* x      = (const float*)d_in[0];
    const float* W_in   = (const float*)d_in[1];
    const float* b_in   = (const float*)d_in[2];
    const float* W_out  = (const float*)d_in[3];
    const float* b_out  = (const float*)d_in[4];
    const float* Wc     = (const float*)d_in[5];
    const float* A      = (const float*)d_in[6];
    const float* V      = (const float*)d_in[7];
    const float* basep  = (const float*)d_in[8];
    const float* alphas = (const float*)d_in[9];
    float* out = (float*)d_out;

    __half *x16, *phi, *plo, *wi16, *wo16, *c16;
    cudaGetSymbolAddress((void**)&x16,  g_x16);
    cudaGetSymbolAddress((void**)&phi,  g_phi);  cudaGetSymbolAddress((void**)&plo,  g_plo);
    cudaGetSymbolAddress((void**)&wi16, g_wi16); cudaGetSymbolAddress((void**)&wo16, g_wo16);
    cudaGetSymbolAddress((void**)&c16,  g_c16);

    cudaFuncSetAttribute(gemm_mma<0>, cudaFuncAttributeMaxDynamicSharedMemorySize, SMEM_GEMM);
    cudaFuncSetAttribute(gemm_mma<1>, cudaFuncAttributeMaxDynamicSharedMemorySize, SMEM_GEMM);

    // 1. conversions
    int n4x = M_TOTAL * DMODEL / 4;
    round_f16<<<n4x / 256, 256>>>(x, x16, n4x);
    int n4w = DMODEL * DMODEL / 4;
    round_f16<<<n4w / 256, 256>>>(W_in,  wi16, n4w);
    round_f16<<<n4w / 256, 256>>>(W_out, wo16, n4w);

    dim3 ggrid(DMODEL / BN, M_TOTAL / BM);   // (8, 64)

    // 2. GEMM1: xproj(hi/lo) = x @ W_in^T + b_in
    gemm_mma<1><<<ggrid, 128, SMEM_GEMM>>>(x16, wi16, b_in, nullptr, phi, plo);

    // 3. middle stage (fused heads), writes concat as fp16
    dka_mid_fused<<<dim3(NSEQ / TILE_N, NHEADS, BSZ), 128>>>(Wc, A, V, basep, alphas);

    // 4. GEMM2: out = concat @ W_out^T + b_out
    gemm_mma<0><<<ggrid, 128, SMEM_GEMM>>>(c16, wo16, b_out, out, nullptr, nullptr);
}